// round 15
// baseline (speedup 1.0000x reference)
#include <cuda_runtime.h>
#include <cuda_fp16.h>
#include <math.h>
#include <stdint.h>

#define NODES 50000
#define EDGES 800000
#define FIN   128
#define FH    256
#define FOUT  10
#define NGRAPH 128
#define SCAN_BLOCKS 49   // ceil(50000/1024)

#define STAGE 40960                  // A(8KB) + W(32KB) per stage, 1KB-aligned
#define FUSED_SMEM (3 * STAGE)       // 122880
#define FUSED_THREADS 768            // 16 consumer warps + 8 producer warps
#define CONS_THREADS 512

__device__ __forceinline__ uint32_t smem_u32(const void* p) {
    uint32_t a;
    asm("{ .reg .u64 t; cvta.to.shared.u64 t, %1; cvt.u32.u64 %0, t; }" : "=r"(a) : "l"(p));
    return a;
}
__device__ __forceinline__ uint32_t sw128(uint32_t off) { return off ^ ((off >> 3) & 0x70); }
__device__ __forceinline__ float2 h2f(uint32_t u) {
    __half2 h = *reinterpret_cast<__half2*>(&u);
    return __half22float2(h);
}
#define BAR_SYNC(id)   asm volatile("bar.sync %0, %1;"   :: "r"(id), "r"(FUSED_THREADS) : "memory")
#define BAR_ARRIVE(id) asm volatile("bar.arrive %0, %1;" :: "r"(id), "r"(FUSED_THREADS) : "memory")

// ================= scratch ==================================================
__device__ __half  g_hA[(size_t)NODES * FH];     // ping
__device__ __half  g_hB[(size_t)NODES * FH];     // pong
__device__ __half  g_x16[(size_t)NODES * FIN];   // dinv-scaled x (fp16)
__device__ __half  g_W0[FH * FIN];               // weights [N=256][K] fp16
__device__ __half  g_W1[FH * FH];
__device__ __half  g_W2[FH * FH];
__device__ float   g_dinv[NODES];
__device__ int     g_deg[NODES];
__device__ int     g_rowptr[NODES + 1];
__device__ int     g_cursor[NODES];
__device__ int     g_bsum[SCAN_BLOCKS];
__device__ int     g_boff[SCAN_BLOCKS];
__device__ int     g_ticket;
__device__ int     g_src[EDGES];
__device__ int     g_gcount[NGRAPH];
__device__ int     g_gstart[NGRAPH + 1];
__device__ int     g_is64;

__device__ __forceinline__ int load_idx(const void* p, size_t i) {
    return g_is64 ? (int)((const long long*)p)[i] : ((const int*)p)[i];
}
__device__ __forceinline__ int rowptr_abs(int i) {
    return g_rowptr[i] + g_boff[i >> 10];
}

// ================= zero + dtype probe =======================================
__global__ void k_zero(const int* __restrict__ ei32) {
    int i = blockIdx.x * blockDim.x + threadIdx.x;
    if (blockIdx.x == 0) {
        __shared__ int nonzero;
        if (threadIdx.x == 0) nonzero = 0;
        __syncthreads();
        int stride = (2 * EDGES) / 256;
        int pos = threadIdx.x * stride + 1;
        if (ei32[pos | 1] != 0) atomicOr(&nonzero, 1);
        __syncthreads();
        if (threadIdx.x == 0) { g_is64 = nonzero ? 0 : 1; g_ticket = 0; }
    }
    if (i < NODES) { g_deg[i] = 0; g_cursor[i] = 0; }
    if (i < NGRAPH) g_gcount[i] = 0;
}

// ================= histograms + weight conversion ===========================
#define NWELEM (256 * FIN + 2 * 256 * FH)
__global__ void k_hist(const void* __restrict__ ei, const void* __restrict__ batch,
                       const float* __restrict__ W0, const float* __restrict__ W1,
                       const float* __restrict__ W2) {
    int i = blockIdx.x * blockDim.x + threadIdx.x;
    if (i < EDGES) atomicAdd(&g_deg[load_idx(ei, (size_t)EDGES + i)], 1);
    if (i < NODES) atomicAdd(&g_gcount[load_idx(batch, i)], 1);
    if (i < NWELEM) {
        float w; __half* dst;
        if (i < 256 * FIN) {
            int n = i / FIN, k = i - n * FIN;
            w = W0[(size_t)k * FH + n]; dst = g_W0 + i;
        } else if (i < 256 * FIN + 256 * FH) {
            int j = i - 256 * FIN;
            int n = j / FH, k = j - n * FH;
            w = W1[(size_t)k * FH + n]; dst = g_W1 + j;
        } else {
            int j = i - 256 * FIN - 256 * FH;
            int n = j / FH, k = j - n * FH;
            w = W2[(size_t)k * FH + n]; dst = g_W2 + j;
        }
        *dst = __float2half(w);
    }
}

// ================= single-kernel scan (last block finishes, race-free) ======
__global__ void __launch_bounds__(1024) k_scan1() {
    __shared__ int wsum[32];
    __shared__ int is_last;
    __shared__ int gs[NGRAPH];
    int t = threadIdx.x, lane = t & 31, w = t >> 5;
    int i = blockIdx.x * 1024 + t;
    int v = 0;
    if (i < NODES) {
        v = g_deg[i];
        g_dinv[i] = rsqrtf((float)v + 1.0f);
    }
    int x = v;
    #pragma unroll
    for (int off = 1; off < 32; off <<= 1) {
        int y = __shfl_up_sync(0xFFFFFFFFu, x, off);
        if (lane >= off) x += y;
    }
    if (lane == 31) wsum[w] = x;
    __syncthreads();
    if (w == 0) {
        int s = wsum[lane];
        #pragma unroll
        for (int off = 1; off < 32; off <<= 1) {
            int y = __shfl_up_sync(0xFFFFFFFFu, s, off);
            if (lane >= off) s += y;
        }
        wsum[lane] = s;
    }
    __syncthreads();
    int woff = (w > 0) ? wsum[w - 1] : 0;
    if (i <= NODES) g_rowptr[i] = woff + x - v;
    if (t == 1023) {
        g_bsum[blockIdx.x] = wsum[31];
        __threadfence();
    }
    __syncthreads();
    if (t == 0) {
        int prev = atomicAdd(&g_ticket, 1);
        is_last = (prev == SCAN_BLOCKS - 1);
        if (is_last) __threadfence();
    }
    __syncthreads();
    if (!is_last) return;
    if (t == 0) {
        int run = 0;
        for (int b = 0; b < SCAN_BLOCKS; b++) { g_boff[b] = run; run += g_bsum[b]; }
    }
    if (t < NGRAPH) gs[t] = g_gcount[t];
    __syncthreads();
    for (int off = 1; off < NGRAPH; off <<= 1) {
        int add = (t >= off && t < NGRAPH) ? gs[t - off] : 0;
        __syncthreads();
        if (t < NGRAPH) gs[t] += add;
        __syncthreads();
    }
    if (t < NGRAPH) {
        g_gstart[t] = gs[t] - g_gcount[t];
        if (t == NGRAPH - 1) g_gstart[NGRAPH] = gs[t];
    }
}

// ================= scatter + dinv-scaled x conversion =======================
__global__ void k_prep(const void* __restrict__ ei, const float* __restrict__ x) {
    int i = blockIdx.x * blockDim.x + threadIdx.x;
    if (i < EDGES) {
        int row = load_idx(ei, i);
        int col = load_idx(ei, (size_t)EDGES + i);
        int pos = atomicAdd(&g_cursor[col], 1);
        g_src[rowptr_abs(col) + pos] = row;
    }
    if (i < NODES * FIN / 4) {
        float4 v = ((const float4*)x)[i];
        float di = g_dinv[(i * 4) >> 7];
        __half2* dst = (__half2*)(g_x16 + (size_t)i * 4);
        dst[0] = __floats2half2_rn(di * v.x, di * v.y);
        dst[1] = __floats2half2_rn(di * v.z, di * v.w);
    }
}

// ================= fused agg + GEMM (warp-specialized) ======================
// CTA: 64 nodes x 256 N. Producers (warps 16..23) aggregate 64-col K-chunks of
// the gathered input into smem + cp.async W chunk; consumers (warps 0..15) run
// HMMA over the 3-stage ring and write relu(+dinv prescale) fp16 output.
template <int K>
__global__ void __launch_bounds__(FUSED_THREADS, 1) k_fused(int layer) {
    extern __shared__ char smem[];
    uint32_t sb = smem_u32(smem);
    int tid = threadIdx.x;
    int m0 = blockIdx.x * 64;
    const int nch = K >> 6;
    const __half* hsrc = (layer == 0) ? g_x16 : (layer == 1) ? g_hA : g_hB;
    __half* hdst = (layer == 1) ? g_hB : g_hA;
    const __half* W = (layer == 0) ? g_W0 : (layer == 1) ? g_W1 : g_W2;

    if (tid >= CONS_THREADS) {
        // ---------------- producer ----------------
        int ptid = tid - CONS_THREADS;        // 0..255
        int g = ptid & 7, nl = ptid >> 3;     // col-group(8 cols), node-in-pass
        for (int c = 0; c < nch; c++) {
            int s = c % 3, k0 = c << 6;
            if (c >= 3) BAR_SYNC(4 + s);
            // W chunk: 256 rows x 128B, SW128
            uint32_t wb = sb + (uint32_t)s * STAGE + 8192u;
            #pragma unroll
            for (int i = 0; i < 8; i++) {
                int idx = ptid + i * 256;
                int r = idx >> 3, v = idx & 7;
                const __half* srcp = W + (size_t)r * K + k0 + v * 8;
                uint32_t dst = wb + sw128((uint32_t)(r * 128 + v * 16));
                unsigned long long gsrc = (unsigned long long)__cvta_generic_to_global((void*)srcp);
                asm volatile("cp.async.cg.shared.global [%0], [%1], 16;" :: "r"(dst), "l"(gsrc));
            }
            asm volatile("cp.async.commit_group;" ::: "memory");
            // aggregate 64 nodes (2 passes of 32), 8 cols per thread
            #pragma unroll
            for (int pass = 0; pass < 2; pass++) {
                int node = m0 + pass * 32 + nl;
                float acc[8] = {0.f, 0.f, 0.f, 0.f, 0.f, 0.f, 0.f, 0.f};
                if (node < NODES) {
                    size_t coff = (size_t)k0 + g * 8;
                    uint4 sv = *(const uint4*)(hsrc + (size_t)node * K + coff);
                    float2 p0 = h2f(sv.x), p1 = h2f(sv.y), p2 = h2f(sv.z), p3 = h2f(sv.w);
                    acc[0] = p0.x; acc[1] = p0.y; acc[2] = p1.x; acc[3] = p1.y;
                    acc[4] = p2.x; acc[5] = p2.y; acc[6] = p3.x; acc[7] = p3.y;
                    int s0 = rowptr_abs(node), e0 = rowptr_abs(node + 1);
                    int j = s0;
                    for (; j + 7 < e0; j += 8) {
                        uint4 q[8];
                        #pragma unroll
                        for (int u = 0; u < 8; u++)
                            q[u] = *(const uint4*)(hsrc + (size_t)g_src[j + u] * K + coff);
                        #pragma unroll
                        for (int u = 0; u < 8; u++) {
                            float2 a0 = h2f(q[u].x), a1 = h2f(q[u].y), a2 = h2f(q[u].z), a3 = h2f(q[u].w);
                            acc[0] += a0.x; acc[1] += a0.y; acc[2] += a1.x; acc[3] += a1.y;
                            acc[4] += a2.x; acc[5] += a2.y; acc[6] += a3.x; acc[7] += a3.y;
                        }
                    }
                    for (; j < e0; j++) {
                        uint4 q = *(const uint4*)(hsrc + (size_t)g_src[j] * K + coff);
                        float2 a0 = h2f(q.x), a1 = h2f(q.y), a2 = h2f(q.z), a3 = h2f(q.w);
                        acc[0] += a0.x; acc[1] += a0.y; acc[2] += a1.x; acc[3] += a1.y;
                        acc[4] += a2.x; acc[5] += a2.y; acc[6] += a3.x; acc[7] += a3.y;
                    }
                    float di = g_dinv[node];
                    #pragma unroll
                    for (int q8 = 0; q8 < 8; q8++) acc[q8] *= di;
                }
                __half2 o[4];
                o[0] = __floats2half2_rn(acc[0], acc[1]);
                o[1] = __floats2half2_rn(acc[2], acc[3]);
                o[2] = __floats2half2_rn(acc[4], acc[5]);
                o[3] = __floats2half2_rn(acc[6], acc[7]);
                uint32_t dst = sb + (uint32_t)s * STAGE +
                               sw128((uint32_t)((pass * 32 + nl) * 128 + g * 16));
                *(uint4*)(smem + (dst - sb)) = *(uint4*)o;
            }
            asm volatile("cp.async.wait_group 0;" ::: "memory");
            asm volatile("membar.cta;" ::: "memory");
            BAR_ARRIVE(1 + s);
        }
        return;
    }

    // ---------------- consumer ----------------
    int w = tid >> 5, lane = tid & 31;
    int wm = w >> 3, wn = w & 7;              // 2 x 8 warp grid, tile 32x32
    int grp = lane >> 3;
    int rr = (lane & 7) + ((grp & 1) << 3);
    int kof = (grp >= 2) ? 16 : 0;

    float acc[2][4][4];
    #pragma unroll
    for (int i = 0; i < 2; i++)
        #pragma unroll
        for (int j = 0; j < 4; j++)
            #pragma unroll
            for (int q = 0; q < 4; q++) acc[i][j][q] = 0.f;

    for (int c = 0; c < nch; c++) {
        int s = c % 3;
        BAR_SYNC(1 + s);
        uint32_t ab = sb + (uint32_t)s * STAGE;
        uint32_t bb = ab + 8192u;
        #pragma unroll
        for (int kk = 0; kk < 4; kk++) {
            uint32_t a[2][4], bf[2][4];
            #pragma unroll
            for (int mt = 0; mt < 2; mt++) {
                uint32_t addr = ab + sw128((uint32_t)((wm * 32 + mt * 16 + rr) * 128 + kk * 32 + kof));
                asm volatile("ldmatrix.sync.aligned.m8n8.x4.shared.b16 {%0,%1,%2,%3}, [%4];"
                    : "=r"(a[mt][0]), "=r"(a[mt][1]), "=r"(a[mt][2]), "=r"(a[mt][3]) : "r"(addr));
            }
            #pragma unroll
            for (int p = 0; p < 2; p++) {
                uint32_t addr = bb + sw128((uint32_t)((wn * 32 + p * 16 + rr) * 128 + kk * 32 + kof));
                asm volatile("ldmatrix.sync.aligned.m8n8.x4.shared.b16 {%0,%1,%2,%3}, [%4];"
                    : "=r"(bf[p][0]), "=r"(bf[p][1]), "=r"(bf[p][2]), "=r"(bf[p][3]) : "r"(addr));
            }
            #pragma unroll
            for (int mt = 0; mt < 2; mt++)
                #pragma unroll
                for (int nt = 0; nt < 4; nt++) {
                    uint32_t b0 = bf[nt >> 1][nt & 1];
                    uint32_t b1 = bf[nt >> 1][(nt & 1) + 2];
                    asm volatile("mma.sync.aligned.m16n8k16.row.col.f32.f16.f16.f32 "
                        "{%0,%1,%2,%3}, {%4,%5,%6,%7}, {%8,%9}, {%0,%1,%2,%3};"
                        : "+f"(acc[mt][nt][0]), "+f"(acc[mt][nt][1]),
                          "+f"(acc[mt][nt][2]), "+f"(acc[mt][nt][3])
                        : "r"(a[mt][0]), "r"(a[mt][1]), "r"(a[mt][2]), "r"(a[mt][3]),
                          "r"(b0), "r"(b1));
                }
        }
        if (c + 3 < nch) BAR_ARRIVE(4 + s);
    }

    // epilogue: relu (+dinv prescale for layers 0,1), fp16 store
    int colb = wn * 32 + 2 * (lane & 3);
    bool prescale = (layer < 2);
    #pragma unroll
    for (int mt = 0; mt < 2; mt++) {
        int row = m0 + wm * 32 + mt * 16 + (lane >> 2);
        float d0 = 1.f, d1 = 1.f;
        if (prescale) {
            if (row < NODES) d0 = g_dinv[row];
            if (row + 8 < NODES) d1 = g_dinv[row + 8];
        }
        #pragma unroll
        for (int nt = 0; nt < 4; nt++) {
            float v0 = d0 * fmaxf(acc[mt][nt][0], 0.f), v1 = d0 * fmaxf(acc[mt][nt][1], 0.f);
            float v2 = d1 * fmaxf(acc[mt][nt][2], 0.f), v3 = d1 * fmaxf(acc[mt][nt][3], 0.f);
            if (row < NODES)
                *(__half2*)(hdst + (size_t)row * FH + colb + nt * 8) = __floats2half2_rn(v0, v1);
            if (row + 8 < NODES)
                *(__half2*)(hdst + (size_t)(row + 8) * FH + colb + nt * 8) = __floats2half2_rn(v2, v3);
        }
    }
}

// ================= fused pool + MLP head (reads g_hA) =======================
__global__ void __launch_bounds__(256) k_poolhead(
        const float* __restrict__ Wm1, const float* __restrict__ bm1,
        const float* __restrict__ Wm2, const float* __restrict__ bm2,
        float* __restrict__ out) {
    __shared__ float4 red[4][64];
    __shared__ float sp[FH];
    __shared__ float sh[FH];
    __shared__ float sl[FOUT];
    __shared__ float s_m, s_lse;
    int g = blockIdx.x;
    int t = threadIdx.x, cg = t & 63, rg = t >> 6;
    int s = g_gstart[g], e = g_gstart[g + 1];
    {
        int c = cg * 4;
        float4 acc = make_float4(0.f, 0.f, 0.f, 0.f);
        for (int i = s + rg; i < e; i += 4) {
            uint2 u = *(const uint2*)(g_hA + (size_t)i * FH + c);
            float2 a0 = h2f(u.x), a1 = h2f(u.y);
            acc.x += a0.x; acc.y += a0.y; acc.z += a1.x; acc.w += a1.y;
        }
        red[rg][cg] = acc;
    }
    __syncthreads();
    if (rg == 0) {
        float4 a0 = red[0][cg], a1 = red[1][cg], a2 = red[2][cg], a3 = red[3][cg];
        int cnt = e - s;
        float inv = 1.0f / (float)(cnt > 0 ? cnt : 1);
        int c = cg * 4;
        sp[c]     = (a0.x + a1.x + a2.x + a3.x) * inv;
        sp[c + 1] = (a0.y + a1.y + a2.y + a3.y) * inv;
        sp[c + 2] = (a0.z + a1.z + a2.z + a3.z) * inv;
        sp[c + 3] = (a0.w + a1.w + a2.w + a3.w) * inv;
    }
    __syncthreads();
    float acc = bm1[t];
    #pragma unroll 8
    for (int k = 0; k < FH; k++) acc += sp[k] * Wm1[k * FH + t];
    sh[t] = acc > 0.f ? acc : 0.f;
    __syncthreads();
    if (t < FOUT) {
        float a = bm2[t];
        for (int k = 0; k < FH; k++) a += sh[k] * Wm2[k * FOUT + t];
        sl[t] = a;
    }
    __syncthreads();
    if (t == 0) {
        float m = sl[0];
        for (int o = 1; o < FOUT; o++) m = fmaxf(m, sl[o]);
        float sum = 0.f;
        for (int o = 0; o < FOUT; o++) sum += expf(sl[o] - m);
        s_m = m; s_lse = logf(sum);
    }
    __syncthreads();
    if (t < FOUT) {
        float v = sl[t];
        out[g * FOUT + t]                     = v - s_m - s_lse;
        out[NGRAPH * FOUT + g * FOUT + t]     = 1.0f / (1.0f + expf(-v));
        out[2 * NGRAPH * FOUT + g * FOUT + t] = v;
    }
}

// ================= launch ===================================================
extern "C" void kernel_launch(void* const* d_in, const int* in_sizes, int n_in,
                              void* d_out, int out_size) {
    const float* x     = (const float*)d_in[0];
    const void*  ei    = d_in[1];
    const void*  batch = d_in[3];
    const float* W0  = (const float*)d_in[4];
    const float* W1  = (const float*)d_in[5];
    const float* W2  = (const float*)d_in[6];
    const float* Wm1 = (const float*)d_in[7];
    const float* bm1 = (const float*)d_in[8];
    const float* Wm2 = (const float*)d_in[9];
    const float* bm2 = (const float*)d_in[10];
    float* out = (float*)d_out;

    cudaFuncSetAttribute(k_fused<FIN>, cudaFuncAttributeMaxDynamicSharedMemorySize, FUSED_SMEM);
    cudaFuncSetAttribute(k_fused<FH>,  cudaFuncAttributeMaxDynamicSharedMemorySize, FUSED_SMEM);

    // ---- graph structure + conversions (5 launches)
    k_zero<<<(NODES + 255) / 256, 256>>>((const int*)ei);
    k_hist<<<(EDGES + 255) / 256, 256>>>(ei, batch, W0, W1, W2);
    k_scan1<<<SCAN_BLOCKS, 1024>>>();
    k_prep<<<(NODES * FIN / 4 + 255) / 256, 256>>>(ei, x);

    int fgrid = (NODES + 63) / 64;   // 782

    // ---- fused layers
    k_fused<FIN><<<fgrid, FUSED_THREADS, FUSED_SMEM>>>(0);
    k_fused<FH><<<fgrid, FUSED_THREADS, FUSED_SMEM>>>(1);
    k_fused<FH><<<fgrid, FUSED_THREADS, FUSED_SMEM>>>(2);

    // ---- fused pool + head
    k_poolhead<<<NGRAPH, 256>>>(Wm1, bm1, Wm2, bm2, out);
}

// round 16
// speedup vs baseline: 1.6692x; 1.6692x over previous
#include <cuda_runtime.h>
#include <cuda_fp16.h>
#include <math.h>
#include <stdint.h>

#define NODES 50000
#define EDGES 800000
#define FIN   128
#define FH    256
#define FOUT  10
#define NGRAPH 128
#define SCAN_BLOCKS 49   // ceil(50000/1024)

__device__ __forceinline__ uint32_t smem_u32(const void* p) {
    uint32_t a;
    asm("{ .reg .u64 t; cvta.to.shared.u64 t, %1; cvt.u32.u64 %0, t; }" : "=r"(a) : "l"(p));
    return a;
}
__device__ __forceinline__ uint32_t sw128(uint32_t off) { return off ^ ((off >> 3) & 0x70); }
__device__ __forceinline__ float2 h2f(uint32_t u) {
    __half2 h = *reinterpret_cast<__half2*>(&u);
    return __half22float2(h);
}

// ================= scratch ==================================================
__device__ __half  g_h[(size_t)NODES * FH];      // layer outputs (prescaled h' L0/L1; plain L2)
__device__ __half  g_x16[(size_t)NODES * FIN];   // dinv-scaled x (fp16)
__device__ __half  g_Ah[(size_t)NODES * FH];     // agg output (GEMM A input)
__device__ __half  g_W0[FH * FIN];               // weights [N=256][K] fp16
__device__ __half  g_W1[FH * FH];
__device__ __half  g_W2[FH * FH];
__device__ float   g_dinv[NODES];
__device__ int     g_deg[NODES];
__device__ int     g_rowptr[NODES + 1];
__device__ int     g_cursor[NODES];
__device__ int     g_bsum[SCAN_BLOCKS];
__device__ int     g_boff[SCAN_BLOCKS];
__device__ int     g_ticket;
__device__ int     g_src[EDGES];
__device__ int     g_gcount[NGRAPH];
__device__ int     g_gstart[NGRAPH + 1];
__device__ int     g_is64;

__device__ __forceinline__ int load_idx(const void* p, size_t i) {
    return g_is64 ? (int)((const long long*)p)[i] : ((const int*)p)[i];
}
__device__ __forceinline__ int rowptr_abs(int i) {
    return g_rowptr[i] + g_boff[i >> 10];
}

// ================= zero + dtype probe =======================================
__global__ void k_zero(const int* __restrict__ ei32) {
    int i = blockIdx.x * blockDim.x + threadIdx.x;
    if (blockIdx.x == 0) {
        __shared__ int nonzero;
        if (threadIdx.x == 0) nonzero = 0;
        __syncthreads();
        int stride = (2 * EDGES) / 256;
        int pos = threadIdx.x * stride + 1;
        if (ei32[pos | 1] != 0) atomicOr(&nonzero, 1);
        __syncthreads();
        if (threadIdx.x == 0) { g_is64 = nonzero ? 0 : 1; g_ticket = 0; }
    }
    if (i < NODES) { g_deg[i] = 0; g_cursor[i] = 0; }
    if (i < NGRAPH) g_gcount[i] = 0;
}

// ================= histograms + weight conversion ===========================
#define NWELEM (256 * FIN + 2 * 256 * FH)
__global__ void k_hist(const void* __restrict__ ei, const void* __restrict__ batch,
                       const float* __restrict__ W0, const float* __restrict__ W1,
                       const float* __restrict__ W2) {
    int i = blockIdx.x * blockDim.x + threadIdx.x;
    if (i < EDGES) atomicAdd(&g_deg[load_idx(ei, (size_t)EDGES + i)], 1);
    if (i < NODES) atomicAdd(&g_gcount[load_idx(batch, i)], 1);
    if (i < NWELEM) {
        float w; __half* dst;
        if (i < 256 * FIN) {
            int n = i / FIN, k = i - n * FIN;
            w = W0[(size_t)k * FH + n]; dst = g_W0 + i;
        } else if (i < 256 * FIN + 256 * FH) {
            int j = i - 256 * FIN;
            int n = j / FH, k = j - n * FH;
            w = W1[(size_t)k * FH + n]; dst = g_W1 + j;
        } else {
            int j = i - 256 * FIN - 256 * FH;
            int n = j / FH, k = j - n * FH;
            w = W2[(size_t)k * FH + n]; dst = g_W2 + j;
        }
        *dst = __float2half(w);
    }
}

// ================= single-kernel scan (last block finishes, race-free) ======
__global__ void __launch_bounds__(1024) k_scan1() {
    __shared__ int wsum[32];
    __shared__ int is_last;
    __shared__ int gs[NGRAPH];
    int t = threadIdx.x, lane = t & 31, w = t >> 5;
    int i = blockIdx.x * 1024 + t;
    int v = 0;
    if (i < NODES) {
        v = g_deg[i];
        g_dinv[i] = rsqrtf((float)v + 1.0f);
    }
    int x = v;
    #pragma unroll
    for (int off = 1; off < 32; off <<= 1) {
        int y = __shfl_up_sync(0xFFFFFFFFu, x, off);
        if (lane >= off) x += y;
    }
    if (lane == 31) wsum[w] = x;
    __syncthreads();
    if (w == 0) {
        int s = wsum[lane];
        #pragma unroll
        for (int off = 1; off < 32; off <<= 1) {
            int y = __shfl_up_sync(0xFFFFFFFFu, s, off);
            if (lane >= off) s += y;
        }
        wsum[lane] = s;
    }
    __syncthreads();
    int woff = (w > 0) ? wsum[w - 1] : 0;
    if (i <= NODES) g_rowptr[i] = woff + x - v;
    if (t == 1023) {
        g_bsum[blockIdx.x] = wsum[31];
        __threadfence();
    }
    __syncthreads();
    if (t == 0) {
        int prev = atomicAdd(&g_ticket, 1);
        is_last = (prev == SCAN_BLOCKS - 1);
        if (is_last) __threadfence();
    }
    __syncthreads();
    if (!is_last) return;
    if (t == 0) {
        int run = 0;
        for (int b = 0; b < SCAN_BLOCKS; b++) { g_boff[b] = run; run += g_bsum[b]; }
    }
    if (t < NGRAPH) gs[t] = g_gcount[t];
    __syncthreads();
    for (int off = 1; off < NGRAPH; off <<= 1) {
        int add = (t >= off && t < NGRAPH) ? gs[t - off] : 0;
        __syncthreads();
        if (t < NGRAPH) gs[t] += add;
        __syncthreads();
    }
    if (t < NGRAPH) {
        g_gstart[t] = gs[t] - g_gcount[t];
        if (t == NGRAPH - 1) g_gstart[NGRAPH] = gs[t];
    }
}

// ================= scatter + dinv-scaled x conversion =======================
__global__ void k_prep(const void* __restrict__ ei, const float* __restrict__ x) {
    int i = blockIdx.x * blockDim.x + threadIdx.x;
    if (i < EDGES) {
        int row = load_idx(ei, i);
        int col = load_idx(ei, (size_t)EDGES + i);
        int pos = atomicAdd(&g_cursor[col], 1);
        g_src[rowptr_abs(col) + pos] = row;
    }
    if (i < NODES * FIN / 4) {
        float4 v = ((const float4*)x)[i];
        float di = g_dinv[(i * 4) >> 7];
        __half2* dst = (__half2*)(g_x16 + (size_t)i * 4);
        dst[0] = __floats2half2_rn(di * v.x, di * v.y);
        dst[1] = __floats2half2_rn(di * v.z, di * v.w);
    }
}

// ================= aggregation (fp16 gather of prescaled h', unroll 8) ======
// agg_i = dinv_i * (h'_i + sum_{j in N(i)} h'_j)
template <int D>
__device__ __forceinline__ void agg_body16(const __half* __restrict__ h, int node, int c) {
    int s = rowptr_abs(node), e = rowptr_abs(node + 1);
    float di = g_dinv[node];
    uint4 sv = *(const uint4*)(h + (size_t)node * D + c);
    float2 p0 = h2f(sv.x), p1 = h2f(sv.y), p2 = h2f(sv.z), p3 = h2f(sv.w);
    float acc[8] = { p0.x, p0.y, p1.x, p1.y, p2.x, p2.y, p3.x, p3.y };
    int j = s;
    for (; j + 7 < e; j += 8) {
        uint4 q[8];
        #pragma unroll
        for (int u = 0; u < 8; u++)
            q[u] = *(const uint4*)(h + (size_t)g_src[j + u] * D + c);
        #pragma unroll
        for (int u = 0; u < 8; u++) {
            float2 a0 = h2f(q[u].x), a1 = h2f(q[u].y), a2 = h2f(q[u].z), a3 = h2f(q[u].w);
            acc[0] += a0.x; acc[1] += a0.y; acc[2] += a1.x; acc[3] += a1.y;
            acc[4] += a2.x; acc[5] += a2.y; acc[6] += a3.x; acc[7] += a3.y;
        }
    }
    for (; j < e; j++) {
        uint4 q = *(const uint4*)(h + (size_t)g_src[j] * D + c);
        float2 a0 = h2f(q.x), a1 = h2f(q.y), a2 = h2f(q.z), a3 = h2f(q.w);
        acc[0] += a0.x; acc[1] += a0.y; acc[2] += a1.x; acc[3] += a1.y;
        acc[4] += a2.x; acc[5] += a2.y; acc[6] += a3.x; acc[7] += a3.y;
    }
    __half2 out4[4];
    out4[0] = __floats2half2_rn(di * acc[0], di * acc[1]);
    out4[1] = __floats2half2_rn(di * acc[2], di * acc[3]);
    out4[2] = __floats2half2_rn(di * acc[4], di * acc[5]);
    out4[3] = __floats2half2_rn(di * acc[6], di * acc[7]);
    *(uint4*)(g_Ah + (size_t)node * D + c) = *(uint4*)out4;
}
__global__ void __launch_bounds__(256) k_agg_x() {
    int node = blockIdx.x * 16 + (threadIdx.x >> 4);
    if (node >= NODES) return;
    agg_body16<FIN>(g_x16, node, (threadIdx.x & 15) * 8);
}
__global__ void __launch_bounds__(256) k_agg_h() {
    int node = blockIdx.x * 8 + (threadIdx.x >> 5);
    if (node >= NODES) return;
    agg_body16<FH>(g_h, node, (threadIdx.x & 31) * 8);
}

// ================= HMMA GEMM (fp16 single-pass, 3-stage pipeline) ===========
// layers 0,1: g_h = dinv * relu(Ah @ W^T)   (prescaled for next agg)
// layer  2:   g_h = relu(Ah @ W^T)          (plain, for pooling)
#define SMEM_TOTAL 98304
__global__ void __launch_bounds__(256, 2) k_mma(int K, int layer) {
    extern __shared__ char smem[];
    uint32_t sb = smem_u32(smem);
    int tid = threadIdx.x, lane = tid & 31, wid = tid >> 5;
    int wm = wid >> 2, wn = wid & 3;
    int m0 = blockIdx.x * 128, bn = blockIdx.y * 128;
    int nch = K >> 6;
    const __half* W = (layer == 0) ? g_W0 : (layer == 1) ? g_W1 : g_W2;

    float acc[4][4][4];
    #pragma unroll
    for (int i = 0; i < 4; i++)
        #pragma unroll
        for (int j = 0; j < 4; j++)
            #pragma unroll
            for (int q = 0; q < 4; q++) acc[i][j][q] = 0.f;

    auto issue = [&](int c) {
        int k0 = c << 6;
        uint32_t ao = (uint32_t)(c % 3) * 32768u;
        uint32_t bo = ao + 16384u;
        #pragma unroll
        for (int i = 0; i < 4; i++) {
            int idx = tid + i * 256;
            int r = idx >> 3, v = idx & 7;
            int gr = m0 + r;
            int ok = gr < NODES;
            const __half* src = g_Ah + (size_t)(ok ? gr : 0) * K + k0 + v * 8;
            uint32_t dst = sb + ao + sw128((uint32_t)(r * 128 + v * 16));
            unsigned long long gs = (unsigned long long)__cvta_generic_to_global((void*)src);
            int sz = ok ? 16 : 0;
            asm volatile("cp.async.cg.shared.global [%0], [%1], 16, %2;" :: "r"(dst), "l"(gs), "r"(sz));
        }
        #pragma unroll
        for (int i = 0; i < 4; i++) {
            int idx = tid + i * 256;
            int r = idx >> 3, v = idx & 7;
            const __half* src = W + (size_t)(bn + r) * K + k0 + v * 8;
            uint32_t dst = sb + bo + sw128((uint32_t)(r * 128 + v * 16));
            unsigned long long gs = (unsigned long long)__cvta_generic_to_global((void*)src);
            asm volatile("cp.async.cg.shared.global [%0], [%1], 16;" :: "r"(dst), "l"(gs));
        }
        asm volatile("cp.async.commit_group;" ::: "memory");
    };

    issue(0);
    if (nch > 1) issue(1);

    int grp = lane >> 3;
    int rr = (lane & 7) + ((grp & 1) << 3);
    int kof = (grp >= 2) ? 16 : 0;

    for (int c = 0; c < nch; c++) {
        if (c + 2 < nch) { issue(c + 2); asm volatile("cp.async.wait_group 2;" ::: "memory"); }
        else if (c + 1 < nch) { asm volatile("cp.async.wait_group 1;" ::: "memory"); }
        else { asm volatile("cp.async.wait_group 0;" ::: "memory"); }
        __syncthreads();
        uint32_t ab = sb + (uint32_t)(c % 3) * 32768u;
        uint32_t bb = ab + 16384u;
        #pragma unroll
        for (int kk = 0; kk < 4; kk++) {
            uint32_t a[4][4], bf[2][4];
            #pragma unroll
            for (int mt = 0; mt < 4; mt++) {
                uint32_t addr = ab + sw128((uint32_t)((wm * 64 + mt * 16 + rr) * 128 + kk * 32 + kof));
                asm volatile("ldmatrix.sync.aligned.m8n8.x4.shared.b16 {%0,%1,%2,%3}, [%4];"
                    : "=r"(a[mt][0]), "=r"(a[mt][1]), "=r"(a[mt][2]), "=r"(a[mt][3]) : "r"(addr));
            }
            #pragma unroll
            for (int p = 0; p < 2; p++) {
                uint32_t addr = bb + sw128((uint32_t)((wn * 32 + p * 16 + rr) * 128 + kk * 32 + kof));
                asm volatile("ldmatrix.sync.aligned.m8n8.x4.shared.b16 {%0,%1,%2,%3}, [%4];"
                    : "=r"(bf[p][0]), "=r"(bf[p][1]), "=r"(bf[p][2]), "=r"(bf[p][3]) : "r"(addr));
            }
            #pragma unroll
            for (int mt = 0; mt < 4; mt++)
                #pragma unroll
                for (int nt = 0; nt < 4; nt++) {
                    uint32_t b0 = bf[nt >> 1][nt & 1];
                    uint32_t b1 = bf[nt >> 1][(nt & 1) + 2];
                    asm volatile("mma.sync.aligned.m16n8k16.row.col.f32.f16.f16.f32 "
                        "{%0,%1,%2,%3}, {%4,%5,%6,%7}, {%8,%9}, {%0,%1,%2,%3};"
                        : "+f"(acc[mt][nt][0]), "+f"(acc[mt][nt][1]),
                          "+f"(acc[mt][nt][2]), "+f"(acc[mt][nt][3])
                        : "r"(a[mt][0]), "r"(a[mt][1]), "r"(a[mt][2]), "r"(a[mt][3]),
                          "r"(b0), "r"(b1));
                }
        }
        __syncthreads();
    }

    // epilogue: relu (+dinv prescale for layers 0,1), fp16 store to g_h
    int colb = bn + wn * 32 + 2 * (lane & 3);
    bool prescale = (layer < 2);
    #pragma unroll
    for (int mt = 0; mt < 4; mt++) {
        int row = m0 + wm * 64 + mt * 16 + (lane >> 2);
        float d0 = 1.f, d1 = 1.f;
        if (prescale) {
            if (row < NODES) d0 = g_dinv[row];
            if (row + 8 < NODES) d1 = g_dinv[row + 8];
        }
        #pragma unroll
        for (int nt = 0; nt < 4; nt++) {
            float v0 = d0 * fmaxf(acc[mt][nt][0], 0.f), v1 = d0 * fmaxf(acc[mt][nt][1], 0.f);
            float v2 = d1 * fmaxf(acc[mt][nt][2], 0.f), v3 = d1 * fmaxf(acc[mt][nt][3], 0.f);
            if (row < NODES)
                *(__half2*)(g_h + (size_t)row * FH + colb + nt * 8) = __floats2half2_rn(v0, v1);
            if (row + 8 < NODES)
                *(__half2*)(g_h + (size_t)(row + 8) * FH + colb + nt * 8) = __floats2half2_rn(v2, v3);
        }
    }
}

// ================= fused pool + MLP head (fp16 input) =======================
__global__ void __launch_bounds__(256) k_poolhead(
        const float* __restrict__ Wm1, const float* __restrict__ bm1,
        const float* __restrict__ Wm2, const float* __restrict__ bm2,
        float* __restrict__ out) {
    __shared__ float4 red[4][64];
    __shared__ float sp[FH];
    __shared__ float sh[FH];
    __shared__ float sl[FOUT];
    __shared__ float s_m, s_lse;
    int g = blockIdx.x;
    int t = threadIdx.x, cg = t & 63, rg = t >> 6;
    int s = g_gstart[g], e = g_gstart[g + 1];
    {
        int c = cg * 4;
        float4 acc = make_float4(0.f, 0.f, 0.f, 0.f);
        for (int i = s + rg; i < e; i += 4) {
            uint2 u = *(const uint2*)(g_h + (size_t)i * FH + c);
            float2 a0 = h2f(u.x), a1 = h2f(u.y);
            acc.x += a0.x; acc.y += a0.y; acc.z += a1.x; acc.w += a1.y;
        }
        red[rg][cg] = acc;
    }
    __syncthreads();
    if (rg == 0) {
        float4 a0 = red[0][cg], a1 = red[1][cg], a2 = red[2][cg], a3 = red[3][cg];
        int cnt = e - s;
        float inv = 1.0f / (float)(cnt > 0 ? cnt : 1);
        int c = cg * 4;
        sp[c]     = (a0.x + a1.x + a2.x + a3.x) * inv;
        sp[c + 1] = (a0.y + a1.y + a2.y + a3.y) * inv;
        sp[c + 2] = (a0.z + a1.z + a2.z + a3.z) * inv;
        sp[c + 3] = (a0.w + a1.w + a2.w + a3.w) * inv;
    }
    __syncthreads();
    float acc = bm1[t];
    #pragma unroll 8
    for (int k = 0; k < FH; k++) acc += sp[k] * Wm1[k * FH + t];
    sh[t] = acc > 0.f ? acc : 0.f;
    __syncthreads();
    if (t < FOUT) {
        float a = bm2[t];
        for (int k = 0; k < FH; k++) a += sh[k] * Wm2[k * FOUT + t];
        sl[t] = a;
    }
    __syncthreads();
    if (t == 0) {
        float m = sl[0];
        for (int o = 1; o < FOUT; o++) m = fmaxf(m, sl[o]);
        float sum = 0.f;
        for (int o = 0; o < FOUT; o++) sum += expf(sl[o] - m);
        s_m = m; s_lse = logf(sum);
    }
    __syncthreads();
    if (t < FOUT) {
        float v = sl[t];
        out[g * FOUT + t]                     = v - s_m - s_lse;
        out[NGRAPH * FOUT + g * FOUT + t]     = 1.0f / (1.0f + expf(-v));
        out[2 * NGRAPH * FOUT + g * FOUT + t] = v;
    }
}

// ================= launch ===================================================
extern "C" void kernel_launch(void* const* d_in, const int* in_sizes, int n_in,
                              void* d_out, int out_size) {
    const float* x     = (const float*)d_in[0];
    const void*  ei    = d_in[1];
    const void*  batch = d_in[3];
    const float* W0  = (const float*)d_in[4];
    const float* W1  = (const float*)d_in[5];
    const float* W2  = (const float*)d_in[6];
    const float* Wm1 = (const float*)d_in[7];
    const float* bm1 = (const float*)d_in[8];
    const float* Wm2 = (const float*)d_in[9];
    const float* bm2 = (const float*)d_in[10];
    float* out = (float*)d_out;

    cudaFuncSetAttribute(k_mma, cudaFuncAttributeMaxDynamicSharedMemorySize, SMEM_TOTAL);

    // ---- graph structure + conversions (4 launches)
    k_zero<<<(NODES + 255) / 256, 256>>>((const int*)ei);
    k_hist<<<(EDGES + 255) / 256, 256>>>(ei, batch, W0, W1, W2);
    k_scan1<<<SCAN_BLOCKS, 1024>>>();
    k_prep<<<(NODES * FIN / 4 + 255) / 256, 256>>>(ei, x);

    dim3 mg((NODES + 127) / 128, 2);

    // ---- layer 0
    k_agg_x<<<(NODES + 15) / 16, 256>>>();
    k_mma<<<mg, 256, SMEM_TOTAL>>>(FIN, 0);
    // ---- layer 1
    k_agg_h<<<(NODES + 7) / 8, 256>>>();
    k_mma<<<mg, 256, SMEM_TOTAL>>>(FH, 1);
    // ---- layer 2
    k_agg_h<<<(NODES + 7) / 8, 256>>>();
    k_mma<<<mg, 256, SMEM_TOTAL>>>(FH, 2);

    // ---- fused pool + head
    k_poolhead<<<NGRAPH, 256>>>(Wm1, bm1, Wm2, bm2, out);
}